// round 16
// baseline (speedup 1.0000x reference)
#include <cuda_runtime.h>
#include <cuda_fp16.h>
#include <math.h>
#include <stdint.h>

#define Bsz  4
#define Ssz  2048
#define Dsz  1024
#define Hsz  16
#define HDsz 64
#define Msz  (Bsz * Ssz)   // 8192

// Scratch (device globals: allocation-free rule) — all fp16
__device__ __half g_Q[Msz * Dsz];    // [B,H,S,hd] (scaled log2e/8)
__device__ __half g_K[Msz * Dsz];    // [B,H,S,hd]
__device__ __half g_Vt[Msz * Dsz];   // [B,H,hd,S] transposed V
__device__ __half g_AO[Msz * Dsz];   // [B,S,H*hd]
__device__ __half g_Xr[Msz * Dsz];   // X rounded to fp16
__device__ __half g_Wq[Dsz * Dsz];
__device__ __half g_Wk[Dsz * Dsz];
__device__ __half g_Wv[Dsz * Dsz];
__device__ __half g_Wo[Dsz * Dsz];

// ===========================================================================
// helpers
// ===========================================================================
__device__ __forceinline__ uint32_t smem_u32(const void* p) {
    uint32_t a;
    asm("{ .reg .u64 t; cvta.to.shared.u64 t, %1; cvt.u32.u64 %0, t; }"
        : "=r"(a) : "l"(p));
    return a;
}
__device__ __forceinline__ uint32_t pack_h2(float a, float b) {
    __half2 h = __floats2half2_rn(a, b);
    return *(uint32_t*)&h;
}
__device__ __forceinline__ void ldsm_x4(uint32_t& r0, uint32_t& r1,
                                        uint32_t& r2, uint32_t& r3, uint32_t a) {
    asm volatile("ldmatrix.sync.aligned.m8n8.x4.shared.b16 {%0,%1,%2,%3}, [%4];"
                 : "=r"(r0), "=r"(r1), "=r"(r2), "=r"(r3) : "r"(a));
}
__device__ __forceinline__ void mma_f16(float* c, const uint32_t* a,
                                        const uint32_t* b) {
    asm volatile(
        "mma.sync.aligned.m16n8k16.row.col.f32.f16.f16.f32 "
        "{%0,%1,%2,%3}, {%4,%5,%6,%7}, {%8,%9}, {%0,%1,%2,%3};"
        : "+f"(c[0]), "+f"(c[1]), "+f"(c[2]), "+f"(c[3])
        : "r"(a[0]), "r"(a[1]), "r"(a[2]), "r"(a[3]), "r"(b[0]), "r"(b[1]));
}
__device__ __forceinline__ void cp16(uint32_t saddr, const void* gaddr) {
    asm volatile("cp.async.cg.shared.global [%0], [%1], 16;"
                 :: "r"(saddr), "l"(gaddr));
}

// ===========================================================================
// fp16 mma.sync GEMM: D[64,128] CTA tile = A[bm:,1024] * W[bn:,1024]^T  (NT)
// 256 threads = 8 warps, warp grid 2(m)x4(n), warp tile 32x32.
// Low-reg config (C=32 regs) -> launch_bounds(256,3): 6 warps/SMSP.
// BK=64 elements, 2-stage ring (55.3KB/CTA, 3 CTAs/SM).
// ===========================================================================
#define BKE       64                        // K elements per stage
#define GROWB     144                       // bytes per smem row
#define ATILE_B   (64 * GROWB)              // 9216
#define WTILE_B   (128 * GROWB)             // 18432
#define GSTAGE_B  (ATILE_B + WTILE_B)       // 27648
#define GSMEM     (2 * GSTAGE_B)            // 55296

struct CFrag { float c[2][4][4]; };         // [mt][nt][4]

__device__ __forceinline__ void h16_gemm_main(const __half* __restrict__ A,
                                              const __half* __restrict__ W,
                                              int bm, int bn, char* smem,
                                              CFrag& C)
{
    const int tid  = threadIdx.x;
    const int wid  = tid >> 5;
    const int lane = tid & 31;
    const int wm   = (wid & 1) * 32;        // warp M origin (0/32)
    const int wn   = (wid >> 1) * 32;       // warp N origin (0/32/64/96)
    const uint32_t sbase = smem_u32(smem);

#pragma unroll
    for (int i = 0; i < 2; i++)
#pragma unroll
        for (int j = 0; j < 4; j++)
#pragma unroll
            for (int q = 0; q < 4; q++) C.c[i][j][q] = 0.0f;

    auto load_stage = [&](int st, int k0) {   // k0 in elements
        const uint32_t sb = sbase + st * GSTAGE_B;
        // A: 64 rows x 8 chunks = 512; 2 per thread
#pragma unroll
        for (int i = 0; i < 2; i++) {
            int id  = tid + i * 256;
            int row = id >> 3;
            int ch  = id & 7;
            cp16(sb + (uint32_t)(row * GROWB + ch * 16),
                 A + (size_t)(bm + row) * 1024 + k0 + ch * 8);
        }
        // W: 128 rows x 8 chunks = 1024; 4 per thread
#pragma unroll
        for (int i = 0; i < 4; i++) {
            int id  = tid + i * 256;
            int row = id >> 3;
            int ch  = id & 7;
            cp16(sb + ATILE_B + (uint32_t)(row * GROWB + ch * 16),
                 W + (size_t)(bn + row) * 1024 + k0 + ch * 8);
        }
        asm volatile("cp.async.commit_group;" ::: "memory");
    };

    load_stage(0, 0);
    load_stage(1, BKE);

    const int a_row = (lane & 7) + ((lane >> 3) & 1) * 8;
    const int a_co  = (lane >> 4) * 16;       // bytes (8 halves)
    const int b_row = (lane & 7) + (lane >> 4) * 8;
    const int b_co  = ((lane >> 3) & 1) * 16; // bytes

    for (int k = 0; k < 16; k++) {
        const int st = k & 1;
        if (k < 15) asm volatile("cp.async.wait_group 1;" ::: "memory");
        else        asm volatile("cp.async.wait_group 0;" ::: "memory");
        __syncthreads();

        const uint32_t sa = sbase + st * GSTAGE_B;
        const uint32_t sw = sa + ATILE_B;
#pragma unroll
        for (int s = 0; s < 4; s++) {         // k16 steps
            const int kb = s * 32;            // bytes
            uint32_t a[2][4], b[4][2];
#pragma unroll
            for (int mt = 0; mt < 2; mt++) {
                int r = wm + mt * 16 + a_row;
                ldsm_x4(a[mt][0], a[mt][1], a[mt][2], a[mt][3],
                        sa + (uint32_t)(r * GROWB + kb + a_co));
            }
#pragma unroll
            for (int p = 0; p < 2; p++) {
                int n = wn + p * 16 + b_row;
                uint32_t r0, r1, r2, r3;
                ldsm_x4(r0, r1, r2, r3,
                        sw + (uint32_t)(n * GROWB + kb + b_co));
                b[2 * p][0] = r0;  b[2 * p][1] = r1;
                b[2 * p + 1][0] = r2;  b[2 * p + 1][1] = r3;
            }
#pragma unroll
            for (int mt = 0; mt < 2; mt++)
#pragma unroll
                for (int nt = 0; nt < 4; nt++)
                    mma_f16(C.c[mt][nt], a[mt], b[nt]);
        }

        __syncthreads();                      // readers done before refill
        if (k + 2 < 16) load_stage(st, (k + 2) * BKE);
    }
}

// ===========================================================================
// QKV projection: grid (8, 128, 3), 256 threads. fp16 outputs.
// z==0: Q scaled by log2(e)/8.  z==2: V stored transposed into g_Vt[bh][d][s].
// ===========================================================================
#define QSCALE 0.18033688011112042f    // log2(e) / 8

__global__ __launch_bounds__(256, 3)
void qkv_mma_kernel()
{
    extern __shared__ char smem[];
    const int bn = blockIdx.x * 128;
    const int bm = blockIdx.y * 64;
    const int z  = blockIdx.z;
    const __half* W = (z == 0) ? g_Wq : (z == 1) ? g_Wk : g_Wv;

    CFrag C;
    h16_gemm_main(g_Xr, W, bm, bn, smem, C);

    const int wid  = threadIdx.x >> 5;
    const int lane = threadIdx.x & 31;
    const int wm = (wid & 1) * 32, wn = (wid >> 1) * 32;

    if (z == 2) {
#pragma unroll
        for (int mt = 0; mt < 2; mt++) {
#pragma unroll
            for (int nt = 0; nt < 4; nt++) {
                int n = bn + wn + nt * 8 + 2 * (lane & 3);
                int h = n >> 6, d = n & 63;
#pragma unroll
                for (int half = 0; half < 2; half++) {
                    int m = bm + wm + mt * 16 + (lane >> 2) + half * 8;
                    int b = m >> 11, s = m & 2047;
                    __half* base =
                        &g_Vt[((size_t)(b * Hsz + h) * HDsz + d) * Ssz + s];
                    base[0]   = __float2half_rn(C.c[mt][nt][2 * half + 0]);
                    base[Ssz] = __float2half_rn(C.c[mt][nt][2 * half + 1]);
                }
            }
        }
    } else {
        __half* Dst = (z == 0) ? g_Q : g_K;
        const float scale = (z == 0) ? QSCALE : 1.0f;
#pragma unroll
        for (int mt = 0; mt < 2; mt++) {
#pragma unroll
            for (int nt = 0; nt < 4; nt++) {
                int n = bn + wn + nt * 8 + 2 * (lane & 3);
                int h = n >> 6, d = n & 63;
#pragma unroll
                for (int half = 0; half < 2; half++) {
                    int m = bm + wm + mt * 16 + (lane >> 2) + half * 8;
                    int b = m >> 11, s = m & 2047;
                    uint32_t v = pack_h2(C.c[mt][nt][2 * half + 0] * scale,
                                         C.c[mt][nt][2 * half + 1] * scale);
                    *(uint32_t*)&Dst[(((size_t)(b * Hsz + h)) * Ssz + s) * HDsz + d] = v;
                }
            }
        }
    }
}

// ===========================================================================
// Output projection: grid (8, 128), 256 threads -> d_out (fp32)
// ===========================================================================
__global__ __launch_bounds__(256, 3)
void out_mma_kernel(float* __restrict__ Out)
{
    extern __shared__ char smem[];
    const int bn = blockIdx.x * 128;
    const int bm = blockIdx.y * 64;

    CFrag C;
    h16_gemm_main(g_AO, g_Wo, bm, bn, smem, C);

    const int wid  = threadIdx.x >> 5;
    const int lane = threadIdx.x & 31;
    const int wm = (wid & 1) * 32, wn = (wid >> 1) * 32;

#pragma unroll
    for (int mt = 0; mt < 2; mt++) {
#pragma unroll
        for (int nt = 0; nt < 4; nt++) {
            int n = bn + wn + nt * 8 + 2 * (lane & 3);
#pragma unroll
            for (int half = 0; half < 2; half++) {
                int m = bm + wm + mt * 16 + (lane >> 2) + half * 8;
                float2 v;
                v.x = C.c[mt][nt][2 * half + 0];
                v.y = C.c[mt][nt][2 * half + 1];
                *(float2*)&Out[(size_t)m * 1024 + n] = v;
            }
        }
    }
}

// ===========================================================================
// Merged fp16-rounding: X (8M) then Wq/Wk/Wv/Wo (1M each), one launch.
// ===========================================================================
#define XN (Msz * Dsz)        // 8388608
#define WN (Dsz * Dsz)        // 1048576

__global__ __launch_bounds__(256)
void round_all_kernel(const float* __restrict__ X,  const float* __restrict__ Wq,
                      const float* __restrict__ Wk, const float* __restrict__ Wv,
                      const float* __restrict__ Wo)
{
    int i = (blockIdx.x * 256 + threadIdx.x) * 4;
    const float* src;
    __half* dst;
    int j;
    if (i < XN)               { src = X;  dst = g_Xr; j = i; }
    else if (i < XN + WN)     { src = Wq; dst = g_Wq; j = i - XN; }
    else if (i < XN + 2 * WN) { src = Wk; dst = g_Wk; j = i - XN - WN; }
    else if (i < XN + 3 * WN) { src = Wv; dst = g_Wv; j = i - XN - 2 * WN; }
    else                      { src = Wo; dst = g_Wo; j = i - XN - 3 * WN; }
    float4 v = *(const float4*)(src + j);
    uint2 o;
    o.x = pack_h2(v.x, v.y);
    o.y = pack_h2(v.z, v.w);
    *(uint2*)(dst + j) = o;
}

// ===========================================================================
// Flash attention, fp16 mma.sync.  grid (32, 64), 128 threads = 4 warps,
// THREE CTAs per SM. CTA: 64 q rows; warp: 16 q rows. KV blocks of 64,
// double-buffered cp.async. Rows 128B data + 16B pad (conflict-free LDSM).
// (unchanged from R14 passing build)
// ===========================================================================
#define ARB2   144
#define KVT_B  (64 * ARB2)                  // 9216
#define ASMEM  (4 * KVT_B + 64 * ARB2)      // 46080

__global__ __launch_bounds__(128, 3)
void attn_mma_kernel()
{
    extern __shared__ char sm[];

    const int tid = threadIdx.x;
    const int w   = tid >> 5;
    const int lane = tid & 31;
    const int qb = blockIdx.x;
    const int bh = blockIdx.y;

    const __half* Qp  = g_Q  + (size_t)bh * (Ssz * HDsz) + (size_t)qb * 64 * HDsz;
    const __half* Kp  = g_K  + (size_t)bh * (Ssz * HDsz);
    const __half* Vtp = g_Vt + (size_t)bh * (HDsz * Ssz);

    const uint32_t sKb = smem_u32(sm);
    const uint32_t sVb = sKb + 2 * KVT_B;
    const uint32_t sPb = sKb + 4 * KVT_B;
    char* sPc = sm + 4 * KVT_B;

    // ---- stage Q (64 rows x 64 halves = 128B rows) ----
#pragma unroll
    for (int i = 0; i < 4; i++) {
        int id = tid + i * 128;            // 0..511
        int r = id >> 3, ch = id & 7;
        *(uint4*)(sPc + r * ARB2 + ch * 16) = *(const uint4*)(Qp + r * 64 + ch * 8);
    }
    __syncthreads();

    const int a_row = (lane & 7) + ((lane >> 3) & 1) * 8;
    const int a_co  = (lane >> 4) * 16;       // bytes
    const int b_row = (lane & 7) + (lane >> 4) * 8;
    const int b_co  = ((lane >> 3) & 1) * 16; // bytes

    uint32_t qf[4][4];
#pragma unroll
    for (int kc = 0; kc < 4; kc++)
        ldsm_x4(qf[kc][0], qf[kc][1], qf[kc][2], qf[kc][3],
                sPb + (uint32_t)((w * 16 + a_row) * ARB2 + kc * 32 + a_co));
    __syncthreads();                          // P region free for reuse

    auto load_kv = [&](int kb, int buf) {
        const __half* kg = Kp  + (size_t)kb * 64 * 64;
        const __half* vg = Vtp + kb * 64;
        const uint32_t kd = sKb + buf * KVT_B;
        const uint32_t vd = sVb + buf * KVT_B;
#pragma unroll
        for (int i = 0; i < 4; i++) {
            int id = tid + i * 128;           // 0..511
            int r = id >> 3, ch = id & 7;
            cp16(kd + r * ARB2 + ch * 16, kg + r * 64 + ch * 8);
            cp16(vd + r * ARB2 + ch * 16, vg + (size_t)r * Ssz + ch * 8);
        }
        asm volatile("cp.async.commit_group;" ::: "memory");
    };

    load_kv(0, 0);
    load_kv(1, 1);

    float m[2] = {-1e30f, -1e30f}, l[2] = {0.0f, 0.0f};
    float of[8][4];
#pragma unroll
    for (int nt = 0; nt < 8; nt++)
#pragma unroll
        for (int q = 0; q < 4; q++) of[nt][q] = 0.0f;

    const uint32_t pw = sPb + (uint32_t)(w * 16) * ARB2;

    for (int kb = 0; kb < 32; kb++) {
        const int buf = kb & 1;
        if (kb < 31) asm volatile("cp.async.wait_group 1;" ::: "memory");
        else         asm volatile("cp.async.wait_group 0;" ::: "memory");
        __syncthreads();

        const uint32_t kbase = sKb + buf * KVT_B;
        const uint32_t vbase = sVb + buf * KVT_B;

        // ---- S = Q K^T (log2 domain) : 32 mma ----
        float sc[8][4];
#pragma unroll
        for (int nt = 0; nt < 8; nt++)
#pragma unroll
            for (int q = 0; q < 4; q++) sc[nt][q] = 0.0f;

#pragma unroll
        for (int kc = 0; kc < 4; kc++) {
#pragma unroll
            for (int p = 0; p < 4; p++) {
                uint32_t r0, r1, r2, r3;
                ldsm_x4(r0, r1, r2, r3,
                        kbase + (uint32_t)((p * 16 + b_row) * ARB2 + kc * 32 + b_co));
                uint32_t b0[2] = {r0, r1}, b1[2] = {r2, r3};
                mma_f16(sc[2 * p],     qf[kc], b0);
                mma_f16(sc[2 * p + 1], qf[kc], b1);
            }
        }

        // ---- online softmax in exp2 domain ----
        float ml0 = -1e30f, ml1 = -1e30f;
#pragma unroll
        for (int nt = 0; nt < 8; nt++) {
            ml0 = fmaxf(ml0, fmaxf(sc[nt][0], sc[nt][1]));
            ml1 = fmaxf(ml1, fmaxf(sc[nt][2], sc[nt][3]));
        }
        ml0 = fmaxf(ml0, __shfl_xor_sync(0xffffffffu, ml0, 1));
        ml0 = fmaxf(ml0, __shfl_xor_sync(0xffffffffu, ml0, 2));
        ml1 = fmaxf(ml1, __shfl_xor_sync(0xffffffffu, ml1, 1));
        ml1 = fmaxf(ml1, __shfl_xor_sync(0xffffffffu, ml1, 2));

        const float mn0 = fmaxf(m[0], ml0), mn1 = fmaxf(m[1], ml1);
        const float a0 = exp2f(m[0] - mn0), a1 = exp2f(m[1] - mn1);
        m[0] = mn0; m[1] = mn1;

        float ll0 = 0.0f, ll1 = 0.0f;
#pragma unroll
        for (int nt = 0; nt < 8; nt++) {
            sc[nt][0] = exp2f(sc[nt][0] - mn0);
            sc[nt][1] = exp2f(sc[nt][1] - mn0);
            sc[nt][2] = exp2f(sc[nt][2] - mn1);
            sc[nt][3] = exp2f(sc[nt][3] - mn1);
            ll0 += sc[nt][0] + sc[nt][1];
            ll1 += sc[nt][2] + sc[nt][3];
        }
        ll0 += __shfl_xor_sync(0xffffffffu, ll0, 1);
        ll0 += __shfl_xor_sync(0xffffffffu, ll0, 2);
        ll1 += __shfl_xor_sync(0xffffffffu, ll1, 1);
        ll1 += __shfl_xor_sync(0xffffffffu, ll1, 2);
        l[0] = l[0] * a0 + ll0;
        l[1] = l[1] * a1 + ll1;

#pragma unroll
        for (int nt = 0; nt < 8; nt++) {
            of[nt][0] *= a0; of[nt][1] *= a0;
            of[nt][2] *= a1; of[nt][3] *= a1;
        }

        // ---- P -> warp-private smem (fp16 RN), reload as A-fragments ----
        {
            const uint32_t r0a = pw + (uint32_t)((lane >> 2) * ARB2 + (lane & 3) * 4);
#pragma unroll
            for (int nt = 0; nt < 8; nt++) {
                uint32_t v0 = pack_h2(sc[nt][0], sc[nt][1]);
                uint32_t v1 = pack_h2(sc[nt][2], sc[nt][3]);
                asm volatile("st.shared.u32 [%0], %1;"
                             :: "r"(r0a + nt * 16), "r"(v0));
                asm volatile("st.shared.u32 [%0], %1;"
                             :: "r"(r0a + 8 * ARB2 + nt * 16), "r"(v1));
            }
        }
        __syncwarp();

        // ---- O += P V : 32 mma ----
#pragma unroll
        for (int kc = 0; kc < 4; kc++) {
            uint32_t af[4];
            ldsm_x4(af[0], af[1], af[2], af[3],
                    pw + (uint32_t)(a_row * ARB2 + kc * 32 + a_co));
#pragma unroll
            for (int p = 0; p < 4; p++) {
                uint32_t r0, r1, r2, r3;
                ldsm_x4(r0, r1, r2, r3,
                        vbase + (uint32_t)((p * 16 + b_row) * ARB2 + kc * 32 + b_co));
                uint32_t b0[2] = {r0, r1}, b1[2] = {r2, r3};
                mma_f16(of[2 * p],     af, b0);
                mma_f16(of[2 * p + 1], af, b1);
            }
        }

        __syncthreads();                   // readers done with buf
        if (kb + 2 < 32) load_kv(kb + 2, buf);
    }

    // ---- epilogue: normalize, fp16, write g_AO ----
    const float inv0 = 1.0f / l[0], inv1 = 1.0f / l[1];
    const int b = bh >> 4, h = bh & 15;
    const int s0 = qb * 64 + w * 16 + (lane >> 2);
#pragma unroll
    for (int nt = 0; nt < 8; nt++) {
        int n = h * 64 + nt * 8 + 2 * (lane & 3);
        uint32_t v0 = pack_h2(of[nt][0] * inv0, of[nt][1] * inv0);
        uint32_t v1 = pack_h2(of[nt][2] * inv1, of[nt][3] * inv1);
        *(uint32_t*)&g_AO[(size_t)(b * Ssz + s0) * Dsz + n]     = v0;
        *(uint32_t*)&g_AO[(size_t)(b * Ssz + s0 + 8) * Dsz + n] = v1;
    }
}

// ===========================================================================
extern "C" void kernel_launch(void* const* d_in, const int* in_sizes, int n_in,
                              void* d_out, int out_size)
{
    const float* X  = (const float*)d_in[0];
    const float* Wq = (const float*)d_in[1];
    const float* Wk = (const float*)d_in[2];
    const float* Wv = (const float*)d_in[3];
    const float* Wo = (const float*)d_in[4];
    float* Out = (float*)d_out;

    cudaFuncSetAttribute(qkv_mma_kernel,
                         cudaFuncAttributeMaxDynamicSharedMemorySize, GSMEM);
    cudaFuncSetAttribute(out_mma_kernel,
                         cudaFuncAttributeMaxDynamicSharedMemorySize, GSMEM);
    cudaFuncSetAttribute(attn_mma_kernel,
                         cudaFuncAttributeMaxDynamicSharedMemorySize, ASMEM);

    round_all_kernel<<<(XN + 4 * WN) / 1024, 256>>>(X, Wq, Wk, Wv, Wo);

    dim3 gq(8, 128, 3);
    qkv_mma_kernel<<<gq, 256, GSMEM>>>();

    dim3 ga(32, 64);
    attn_mma_kernel<<<ga, 128, ASMEM>>>();

    dim3 go(8, 128);
    out_mma_kernel<<<go, 256, GSMEM>>>(Out);
}

// round 17
// speedup vs baseline: 1.0357x; 1.0357x over previous
#include <cuda_runtime.h>
#include <cuda_fp16.h>
#include <math.h>
#include <stdint.h>

#define Bsz  4
#define Ssz  2048
#define Dsz  1024
#define Hsz  16
#define HDsz 64
#define Msz  (Bsz * Ssz)   // 8192

// Scratch (device globals: allocation-free rule) — all fp16
__device__ __half g_Q[Msz * Dsz];    // [B,H,S,hd] (scaled log2e/8)
__device__ __half g_K[Msz * Dsz];    // [B,H,S,hd]
__device__ __half g_Vt[Msz * Dsz];   // [B,H,hd,S] transposed V
__device__ __half g_AO[Msz * Dsz];   // [B,S,H*hd]
__device__ __half g_Xr[Msz * Dsz];   // X rounded to fp16
__device__ __half g_Wq[Dsz * Dsz];
__device__ __half g_Wk[Dsz * Dsz];
__device__ __half g_Wv[Dsz * Dsz];
__device__ __half g_Wo[Dsz * Dsz];

// ===========================================================================
// helpers
// ===========================================================================
__device__ __forceinline__ uint32_t smem_u32(const void* p) {
    uint32_t a;
    asm("{ .reg .u64 t; cvta.to.shared.u64 t, %1; cvt.u32.u64 %0, t; }"
        : "=r"(a) : "l"(p));
    return a;
}
__device__ __forceinline__ uint32_t pack_h2(float a, float b) {
    __half2 h = __floats2half2_rn(a, b);
    return *(uint32_t*)&h;
}
__device__ __forceinline__ void ldsm_x4(uint32_t& r0, uint32_t& r1,
                                        uint32_t& r2, uint32_t& r3, uint32_t a) {
    asm volatile("ldmatrix.sync.aligned.m8n8.x4.shared.b16 {%0,%1,%2,%3}, [%4];"
                 : "=r"(r0), "=r"(r1), "=r"(r2), "=r"(r3) : "r"(a));
}
__device__ __forceinline__ void mma_f16(float* c, const uint32_t* a,
                                        const uint32_t* b) {
    asm volatile(
        "mma.sync.aligned.m16n8k16.row.col.f32.f16.f16.f32 "
        "{%0,%1,%2,%3}, {%4,%5,%6,%7}, {%8,%9}, {%0,%1,%2,%3};"
        : "+f"(c[0]), "+f"(c[1]), "+f"(c[2]), "+f"(c[3])
        : "r"(a[0]), "r"(a[1]), "r"(a[2]), "r"(a[3]), "r"(b[0]), "r"(b[1]));
}
__device__ __forceinline__ void cp16(uint32_t saddr, const void* gaddr) {
    asm volatile("cp.async.cg.shared.global [%0], [%1], 16;"
                 :: "r"(saddr), "l"(gaddr));
}

// ===========================================================================
// fp16 mma.sync GEMM: D[128,128] = A[bm:,1024] * W[bn:,1024]^T  (NT)
// 256 threads = 8 warps, warp tile 64x32. BK=64 elements (128B rows + 16 pad).
// 3-stage cp.async ring, ONE syncthreads/iter, refill-before-compute.
// (R14 winning config)
// ===========================================================================
#define BKE       64                        // K elements per stage
#define GROWB     144                       // bytes per smem row
#define GTILE_B   (128 * GROWB)             // 18432
#define GSTAGE_B  (2 * GTILE_B)             // 36864
#define GSMEM     (3 * GSTAGE_B)            // 110592

struct CFrag { float c[4][4][4]; };         // [mt][nt][4]

__device__ __forceinline__ void h16_gemm_main(const __half* __restrict__ A,
                                              const __half* __restrict__ W,
                                              int bm, int bn, char* smem,
                                              CFrag& C)
{
    const int tid  = threadIdx.x;
    const int wid  = tid >> 5;
    const int lane = tid & 31;
    const int wm   = (wid & 1) * 64;
    const int wn   = (wid >> 1) * 32;
    const uint32_t sbase = smem_u32(smem);

#pragma unroll
    for (int i = 0; i < 4; i++)
#pragma unroll
        for (int j = 0; j < 4; j++)
#pragma unroll
            for (int q = 0; q < 4; q++) C.c[i][j][q] = 0.0f;

    auto load_stage = [&](int st, int k0) {   // k0 in elements
        const uint32_t sb = sbase + st * GSTAGE_B;
#pragma unroll
        for (int i = 0; i < 4; i++) {
            int id  = tid + i * 256;          // 0..1023
            int row = id >> 3;                // 0..127
            int ch  = id & 7;                 // 16B chunk (8 halves)
            uint32_t so = (uint32_t)(row * GROWB + ch * 16);
            cp16(sb + so,            A + (size_t)(bm + row) * 1024 + k0 + ch * 8);
            cp16(sb + GTILE_B + so,  W + (size_t)(bn + row) * 1024 + k0 + ch * 8);
        }
        asm volatile("cp.async.commit_group;" ::: "memory");
    };

    load_stage(0, 0);
    load_stage(1, BKE);

    const int a_row = (lane & 7) + ((lane >> 3) & 1) * 8;
    const int a_co  = (lane >> 4) * 16;       // bytes (8 halves)
    const int b_row = (lane & 7) + (lane >> 4) * 8;
    const int b_co  = ((lane >> 3) & 1) * 16; // bytes

    int st = 0;
    for (int k = 0; k < 16; k++) {
        if (k < 15) asm volatile("cp.async.wait_group 1;" ::: "memory");
        else        asm volatile("cp.async.wait_group 0;" ::: "memory");
        __syncthreads();
        if (k + 2 < 16) {
            int nb = st + 2; if (nb >= 3) nb -= 3;
            load_stage(nb, (k + 2) * BKE);
        }

        const uint32_t sa = sbase + st * GSTAGE_B;
        const uint32_t sw = sa + GTILE_B;
#pragma unroll
        for (int s = 0; s < 4; s++) {         // k16 steps
            const int kb = s * 32;            // bytes
            uint32_t a[4][4], b[4][2];
#pragma unroll
            for (int mt = 0; mt < 4; mt++) {
                int r = wm + mt * 16 + a_row;
                ldsm_x4(a[mt][0], a[mt][1], a[mt][2], a[mt][3],
                        sa + (uint32_t)(r * GROWB + kb + a_co));
            }
#pragma unroll
            for (int p = 0; p < 2; p++) {
                int n = wn + p * 16 + b_row;
                uint32_t r0, r1, r2, r3;
                ldsm_x4(r0, r1, r2, r3,
                        sw + (uint32_t)(n * GROWB + kb + b_co));
                b[2 * p][0] = r0;  b[2 * p][1] = r1;
                b[2 * p + 1][0] = r2;  b[2 * p + 1][1] = r3;
            }
#pragma unroll
            for (int mt = 0; mt < 4; mt++)
#pragma unroll
                for (int nt = 0; nt < 4; nt++)
                    mma_f16(C.c[mt][nt], a[mt], b[nt]);
        }

        if (++st == 3) st = 0;
    }
}

// ===========================================================================
// QKV projection: grid (8, 64, 3), 256 threads. fp16 outputs.
// z==0: Q scaled by log2(e)/8.  z==2: V stored transposed into g_Vt[bh][d][s].
// ===========================================================================
#define QSCALE 0.18033688011112042f    // log2(e) / 8

__global__ __launch_bounds__(256, 2)
void qkv_mma_kernel()
{
    extern __shared__ char smem[];
    const int bn = blockIdx.x * 128;
    const int bm = blockIdx.y * 128;
    const int z  = blockIdx.z;
    const __half* W = (z == 0) ? g_Wq : (z == 1) ? g_Wk : g_Wv;

    CFrag C;
    h16_gemm_main(g_Xr, W, bm, bn, smem, C);

    const int wid  = threadIdx.x >> 5;
    const int lane = threadIdx.x & 31;
    const int wm = (wid & 1) * 64, wn = (wid >> 1) * 32;

    if (z == 2) {
#pragma unroll
        for (int mt = 0; mt < 4; mt++) {
#pragma unroll
            for (int nt = 0; nt < 4; nt++) {
                int n = bn + wn + nt * 8 + 2 * (lane & 3);
                int h = n >> 6, d = n & 63;
#pragma unroll
                for (int half = 0; half < 2; half++) {
                    int m = bm + wm + mt * 16 + (lane >> 2) + half * 8;
                    int b = m >> 11, s = m & 2047;
                    __half* base =
                        &g_Vt[((size_t)(b * Hsz + h) * HDsz + d) * Ssz + s];
                    base[0]   = __float2half_rn(C.c[mt][nt][2 * half + 0]);
                    base[Ssz] = __float2half_rn(C.c[mt][nt][2 * half + 1]);
                }
            }
        }
    } else {
        __half* Dst = (z == 0) ? g_Q : g_K;
        const float scale = (z == 0) ? QSCALE : 1.0f;
#pragma unroll
        for (int mt = 0; mt < 4; mt++) {
#pragma unroll
            for (int nt = 0; nt < 4; nt++) {
                int n = bn + wn + nt * 8 + 2 * (lane & 3);
                int h = n >> 6, d = n & 63;
#pragma unroll
                for (int half = 0; half < 2; half++) {
                    int m = bm + wm + mt * 16 + (lane >> 2) + half * 8;
                    int b = m >> 11, s = m & 2047;
                    uint32_t v = pack_h2(C.c[mt][nt][2 * half + 0] * scale,
                                         C.c[mt][nt][2 * half + 1] * scale);
                    *(uint32_t*)&Dst[(((size_t)(b * Hsz + h)) * Ssz + s) * HDsz + d] = v;
                }
            }
        }
    }
}

// ===========================================================================
// Output projection: grid (8, 64), 256 threads -> d_out (fp32)
// ===========================================================================
__global__ __launch_bounds__(256, 2)
void out_mma_kernel(float* __restrict__ Out)
{
    extern __shared__ char smem[];
    const int bn = blockIdx.x * 128;
    const int bm = blockIdx.y * 128;

    CFrag C;
    h16_gemm_main(g_AO, g_Wo, bm, bn, smem, C);

    const int wid  = threadIdx.x >> 5;
    const int lane = threadIdx.x & 31;
    const int wm = (wid & 1) * 64, wn = (wid >> 1) * 32;

#pragma unroll
    for (int mt = 0; mt < 4; mt++) {
#pragma unroll
        for (int nt = 0; nt < 4; nt++) {
            int n = bn + wn + nt * 8 + 2 * (lane & 3);
#pragma unroll
            for (int half = 0; half < 2; half++) {
                int m = bm + wm + mt * 16 + (lane >> 2) + half * 8;
                float2 v;
                v.x = C.c[mt][nt][2 * half + 0];
                v.y = C.c[mt][nt][2 * half + 1];
                *(float2*)&Out[(size_t)m * 1024 + n] = v;
            }
        }
    }
}

// ===========================================================================
// Merged fp16-rounding: X (8M) then Wq/Wk/Wv/Wo (1M each), one launch.
// ===========================================================================
#define XN (Msz * Dsz)        // 8388608
#define WN (Dsz * Dsz)        // 1048576

__global__ __launch_bounds__(256)
void round_all_kernel(const float* __restrict__ X,  const float* __restrict__ Wq,
                      const float* __restrict__ Wk, const float* __restrict__ Wv,
                      const float* __restrict__ Wo)
{
    int i = (blockIdx.x * 256 + threadIdx.x) * 4;
    const float* src;
    __half* dst;
    int j;
    if (i < XN)               { src = X;  dst = g_Xr; j = i; }
    else if (i < XN + WN)     { src = Wq; dst = g_Wq; j = i - XN; }
    else if (i < XN + 2 * WN) { src = Wk; dst = g_Wk; j = i - XN - WN; }
    else if (i < XN + 3 * WN) { src = Wv; dst = g_Wv; j = i - XN - 2 * WN; }
    else                      { src = Wo; dst = g_Wo; j = i - XN - 3 * WN; }
    float4 v = *(const float4*)(src + j);
    uint2 o;
    o.x = pack_h2(v.x, v.y);
    o.y = pack_h2(v.z, v.w);
    *(uint2*)(dst + j) = o;
}

// ===========================================================================
// Flash attention, fp16 mma.sync.  grid (32, 64), 128 threads = 4 warps,
// THREE CTAs per SM. CTA: 64 q rows; warp: 16 q rows. KV blocks of 64.
// NEW: 3-buffer cp.async ring, ONE syncthreads/iter, refill-before-compute.
// Rows 128B data + 16B pad (conflict-free LDSM).
// ===========================================================================
#define ARB2   144
#define KVT_B  (64 * ARB2)                  // 9216
#define ASMEM  (6 * KVT_B + 64 * ARB2)      // 64512 (3 CTAs/SM: 193.5 KB)

__global__ __launch_bounds__(128, 3)
void attn_mma_kernel()
{
    extern __shared__ char sm[];

    const int tid = threadIdx.x;
    const int w   = tid >> 5;
    const int lane = tid & 31;
    const int qb = blockIdx.x;
    const int bh = blockIdx.y;

    const __half* Qp  = g_Q  + (size_t)bh * (Ssz * HDsz) + (size_t)qb * 64 * HDsz;
    const __half* Kp  = g_K  + (size_t)bh * (Ssz * HDsz);
    const __half* Vtp = g_Vt + (size_t)bh * (HDsz * Ssz);

    const uint32_t sKb = smem_u32(sm);
    const uint32_t sVb = sKb + 3 * KVT_B;
    const uint32_t sPb = sKb + 6 * KVT_B;
    char* sPc = sm + 6 * KVT_B;

    // ---- stage Q (64 rows x 64 halves = 128B rows) ----
#pragma unroll
    for (int i = 0; i < 4; i++) {
        int id = tid + i * 128;            // 0..511
        int r = id >> 3, ch = id & 7;
        *(uint4*)(sPc + r * ARB2 + ch * 16) = *(const uint4*)(Qp + r * 64 + ch * 8);
    }
    __syncthreads();

    const int a_row = (lane & 7) + ((lane >> 3) & 1) * 8;
    const int a_co  = (lane >> 4) * 16;       // bytes
    const int b_row = (lane & 7) + (lane >> 4) * 8;
    const int b_co  = ((lane >> 3) & 1) * 16; // bytes

    uint32_t qf[4][4];
#pragma unroll
    for (int kc = 0; kc < 4; kc++)
        ldsm_x4(qf[kc][0], qf[kc][1], qf[kc][2], qf[kc][3],
                sPb + (uint32_t)((w * 16 + a_row) * ARB2 + kc * 32 + a_co));
    __syncthreads();                          // P region free for reuse

    auto load_kv = [&](int kb, int buf) {
        const __half* kg = Kp  + (size_t)kb * 64 * 64;
        const __half* vg = Vtp + kb * 64;
        const uint32_t kd = sKb + buf * KVT_B;
        const uint32_t vd = sVb + buf * KVT_B;
#pragma unroll
        for (int i = 0; i < 4; i++) {
            int id = tid + i * 128;           // 0..511
            int r = id >> 3, ch = id & 7;
            cp16(kd + r * ARB2 + ch * 16, kg + r * 64 + ch * 8);
            cp16(vd + r * ARB2 + ch * 16, vg + (size_t)r * Ssz + ch * 8);
        }
        asm volatile("cp.async.commit_group;" ::: "memory");
    };

    load_kv(0, 0);
    load_kv(1, 1);

    float m[2] = {-1e30f, -1e30f}, l[2] = {0.0f, 0.0f};
    float of[8][4];
#pragma unroll
    for (int nt = 0; nt < 8; nt++)
#pragma unroll
        for (int q = 0; q < 4; q++) of[nt][q] = 0.0f;

    const uint32_t pw = sPb + (uint32_t)(w * 16) * ARB2;

    int buf = 0;
    for (int kb = 0; kb < 32; kb++) {
        // pending groups at top: {kb, kb+1}
        if (kb < 31) asm volatile("cp.async.wait_group 1;" ::: "memory");
        else         asm volatile("cp.async.wait_group 0;" ::: "memory");
        __syncthreads();     // slot kb visible; readers of slot (kb+2)%3 done (iter kb-1)
        if (kb + 2 < 32) {
            int nb = buf + 2; if (nb >= 3) nb -= 3;
            load_kv(kb + 2, nb);              // overlaps this iteration's compute
        }

        const uint32_t kbase = sKb + buf * KVT_B;
        const uint32_t vbase = sVb + buf * KVT_B;

        // ---- S = Q K^T (log2 domain) : 32 mma ----
        float sc[8][4];
#pragma unroll
        for (int nt = 0; nt < 8; nt++)
#pragma unroll
            for (int q = 0; q < 4; q++) sc[nt][q] = 0.0f;

#pragma unroll
        for (int kc = 0; kc < 4; kc++) {
#pragma unroll
            for (int p = 0; p < 4; p++) {
                uint32_t r0, r1, r2, r3;
                ldsm_x4(r0, r1, r2, r3,
                        kbase + (uint32_t)((p * 16 + b_row) * ARB2 + kc * 32 + b_co));
                uint32_t b0[2] = {r0, r1}, b1[2] = {r2, r3};
                mma_f16(sc[2 * p],     qf[kc], b0);
                mma_f16(sc[2 * p + 1], qf[kc], b1);
            }
        }

        // ---- online softmax in exp2 domain ----
        float ml0 = -1e30f, ml1 = -1e30f;
#pragma unroll
        for (int nt = 0; nt < 8; nt++) {
            ml0 = fmaxf(ml0, fmaxf(sc[nt][0], sc[nt][1]));
            ml1 = fmaxf(ml1, fmaxf(sc[nt][2], sc[nt][3]));
        }
        ml0 = fmaxf(ml0, __shfl_xor_sync(0xffffffffu, ml0, 1));
        ml0 = fmaxf(ml0, __shfl_xor_sync(0xffffffffu, ml0, 2));
        ml1 = fmaxf(ml1, __shfl_xor_sync(0xffffffffu, ml1, 1));
        ml1 = fmaxf(ml1, __shfl_xor_sync(0xffffffffu, ml1, 2));

        const float mn0 = fmaxf(m[0], ml0), mn1 = fmaxf(m[1], ml1);
        const float a0 = exp2f(m[0] - mn0), a1 = exp2f(m[1] - mn1);
        m[0] = mn0; m[1] = mn1;

        float ll0 = 0.0f, ll1 = 0.0f;
#pragma unroll
        for (int nt = 0; nt < 8; nt++) {
            sc[nt][0] = exp2f(sc[nt][0] - mn0);
            sc[nt][1] = exp2f(sc[nt][1] - mn0);
            sc[nt][2] = exp2f(sc[nt][2] - mn1);
            sc[nt][3] = exp2f(sc[nt][3] - mn1);
            ll0 += sc[nt][0] + sc[nt][1];
            ll1 += sc[nt][2] + sc[nt][3];
        }
        ll0 += __shfl_xor_sync(0xffffffffu, ll0, 1);
        ll0 += __shfl_xor_sync(0xffffffffu, ll0, 2);
        ll1 += __shfl_xor_sync(0xffffffffu, ll1, 1);
        ll1 += __shfl_xor_sync(0xffffffffu, ll1, 2);
        l[0] = l[0] * a0 + ll0;
        l[1] = l[1] * a1 + ll1;

#pragma unroll
        for (int nt = 0; nt < 8; nt++) {
            of[nt][0] *= a0; of[nt][1] *= a0;
            of[nt][2] *= a1; of[nt][3] *= a1;
        }

        // ---- P -> warp-private smem (fp16 RN), reload as A-fragments ----
        {
            const uint32_t r0a = pw + (uint32_t)((lane >> 2) * ARB2 + (lane & 3) * 4);
#pragma unroll
            for (int nt = 0; nt < 8; nt++) {
                uint32_t v0 = pack_h2(sc[nt][0], sc[nt][1]);
                uint32_t v1 = pack_h2(sc[nt][2], sc[nt][3]);
                asm volatile("st.shared.u32 [%0], %1;"
                             :: "r"(r0a + nt * 16), "r"(v0));
                asm volatile("st.shared.u32 [%0], %1;"
                             :: "r"(r0a + 8 * ARB2 + nt * 16), "r"(v1));
            }
        }
        __syncwarp();

        // ---- O += P V : 32 mma ----
#pragma unroll
        for (int kc = 0; kc < 4; kc++) {
            uint32_t af[4];
            ldsm_x4(af[0], af[1], af[2], af[3],
                    pw + (uint32_t)(a_row * ARB2 + kc * 32 + a_co));
#pragma unroll
            for (int p = 0; p < 4; p++) {
                uint32_t r0, r1, r2, r3;
                ldsm_x4(r0, r1, r2, r3,
                        vbase + (uint32_t)((p * 16 + b_row) * ARB2 + kc * 32 + b_co));
                uint32_t b0[2] = {r0, r1}, b1[2] = {r2, r3};
                mma_f16(of[2 * p],     af, b0);
                mma_f16(of[2 * p + 1], af, b1);
            }
        }

        if (++buf == 3) buf = 0;
    }

    // ---- epilogue: normalize, fp16, write g_AO ----
    const float inv0 = 1.0f / l[0], inv1 = 1.0f / l[1];
    const int b = bh >> 4, h = bh & 15;
    const int s0 = qb * 64 + w * 16 + (lane >> 2);
#pragma unroll
    for (int nt = 0; nt < 8; nt++) {
        int n = h * 64 + nt * 8 + 2 * (lane & 3);
        uint32_t v0 = pack_h2(of[nt][0] * inv0, of[nt][1] * inv0);
        uint32_t v1 = pack_h2(of[nt][2] * inv1, of[nt][3] * inv1);
        *(uint32_t*)&g_AO[(size_t)(b * Ssz + s0) * Dsz + n]     = v0;
        *(uint32_t*)&g_AO[(size_t)(b * Ssz + s0 + 8) * Dsz + n] = v1;
    }
}

// ===========================================================================
extern "C" void kernel_launch(void* const* d_in, const int* in_sizes, int n_in,
                              void* d_out, int out_size)
{
    const float* X  = (const float*)d_in[0];
    const float* Wq = (const float*)d_in[1];
    const float* Wk = (const float*)d_in[2];
    const float* Wv = (const float*)d_in[3];
    const float* Wo = (const float*)d_in[4];
    float* Out = (float*)d_out;

    cudaFuncSetAttribute(qkv_mma_kernel,
                         cudaFuncAttributeMaxDynamicSharedMemorySize, GSMEM);
    cudaFuncSetAttribute(out_mma_kernel,
                         cudaFuncAttributeMaxDynamicSharedMemorySize, GSMEM);
    cudaFuncSetAttribute(attn_mma_kernel,
                         cudaFuncAttributeMaxDynamicSharedMemorySize, ASMEM);

    round_all_kernel<<<(XN + 4 * WN) / 1024, 256>>>(X, Wq, Wk, Wv, Wo);

    dim3 gq(8, 64, 3);
    qkv_mma_kernel<<<gq, 256, GSMEM>>>();

    dim3 ga(32, 64);
    attn_mma_kernel<<<ga, 128, ASMEM>>>();

    dim3 go(8, 64);
    out_mma_kernel<<<go, 256, GSMEM>>>(Out);
}